// round 11
// baseline (speedup 1.0000x reference)
#include <cuda_runtime.h>
#include <cstdint>

#define NDIM   4096
#define GRID   148          // one block per SM — co-residency guaranteed
#define NTHR   256
#define DSTG   4            // pipeline stages (W+M row pairs)
#define STG_BYTES (2 * NDIM * 4)          // 32 KB per stage
#define SMEM_BYTES (DSTG * STG_BYTES + NDIM * 4 + 64)  // stages + sS + red/mbar

// Inter-layer spike vectors + barrier state (no allocation).
__device__ float g_s0[NDIM];
__device__ float g_s1[NDIM];
__device__ unsigned g_epoch;   // monotonic across launches
__device__ unsigned g_cnt;

__device__ __forceinline__ uint32_t smem_u32(const void* p) {
    uint32_t a;
    asm("{ .reg .u64 t; cvta.to.shared.u64 t, %1; cvt.u32.u64 %0, t; }"
        : "=r"(a) : "l"(p));
    return a;
}
__device__ __forceinline__ void mbar_init(uint32_t a, uint32_t cnt) {
    asm volatile("mbarrier.init.shared.b64 [%0], %1;" :: "r"(a), "r"(cnt) : "memory");
}
__device__ __forceinline__ void mbar_expect_tx(uint32_t a, uint32_t bytes) {
    asm volatile("mbarrier.arrive.expect_tx.shared.b64 _, [%0], %1;"
                 :: "r"(a), "r"(bytes) : "memory");
}
__device__ __forceinline__ void bulk_g2s(uint32_t dst, const void* src,
                                         uint32_t bytes, uint32_t mbar) {
    asm volatile(
        "cp.async.bulk.shared::cta.global.mbarrier::complete_tx::bytes "
        "[%0], [%1], %2, [%3];"
        :: "r"(dst), "l"(src), "r"(bytes), "r"(mbar) : "memory");
}
__device__ __forceinline__ void mbar_wait(uint32_t a, uint32_t parity) {
    asm volatile(
        "{\n\t"
        ".reg .pred P;\n\t"
        "WAIT_%=: \n\t"
        "mbarrier.try_wait.parity.acquire.cta.shared::cta.b64 P, [%0], %1, 0x989680;\n\t"
        "@P bra.uni DONE_%=;\n\t"
        "bra.uni WAIT_%=;\n\t"
        "DONE_%=: \n\t"
        "}"
        :: "r"(a), "r"(parity) : "memory");
}
__device__ __forceinline__ void fence_proxy_async_s() {
    asm volatile("fence.proxy.async.shared::cta;" ::: "memory");
}

// Device-wide epoch barrier. Safe: grid == 148 blocks, 1/SM, all co-resident.
__device__ __forceinline__ void grid_bar(unsigned target) {
    __syncthreads();
    if (threadIdx.x == 0) {
        __threadfence();
        if (atomicAdd(&g_cnt, 1u) == GRID - 1) {
            g_cnt = 0;
            __threadfence();
            atomicExch(&g_epoch, target);
        } else {
            while (*(volatile unsigned*)&g_epoch < target) __nanosleep(64);
        }
        __threadfence();
    }
    __syncthreads();
}

__global__ __launch_bounds__(NTHR, 1)
void snn_k(const float* __restrict__ x,  const float* __restrict__ u,
           const float* __restrict__ W0, const float* __restrict__ W1,
           const float* __restrict__ W2, const float* __restrict__ M0,
           const float* __restrict__ M1, const float* __restrict__ M2,
           const int* __restrict__ Tp,   float* __restrict__ out) {
    extern __shared__ char sm[];
    float* sS  = (float*)(sm + DSTG * STG_BYTES);           // 16 KB spike vec
    float* red = (float*)(sm + DSTG * STG_BYTES + NDIM * 4);
    const uint32_t mbar0 = smem_u32(sm + DSTG * STG_BYTES + NDIM * 4 + 32);

    const int bid = blockIdx.x;
    const int tid = threadIdx.x;
    const int c = (NDIM - bid + GRID - 1) / GRID;   // rows per layer (27/28)
    const int total = 3 * c;

    if (tid == 0)
        for (int s = 0; s < DSTG; s++) mbar_init(mbar0 + s * 8, 1);
    __syncthreads();

    const unsigned base = *(volatile unsigned*)&g_epoch;  // stable: read before any release

    // Issue TMA pair for flat iteration `it` (layer-major over this block's rows).
    auto issue = [&](int it) {
        const int layer = it / c;
        const int row   = bid + GRID * (it - layer * c);
        const float* Wp = (layer == 0) ? W0 : (layer == 1) ? W1 : W2;
        const float* Mp = (layer == 0) ? M0 : (layer == 1) ? M1 : M2;
        const int stage = it & (DSTG - 1);
        const uint32_t mb  = mbar0 + stage * 8;
        const uint32_t dst = smem_u32(sm + stage * STG_BYTES);
        mbar_expect_tx(mb, STG_BYTES);
        bulk_g2s(dst,             Wp + (size_t)row * NDIM, NDIM * 4, mb);
        bulk_g2s(dst + NDIM * 4,  Mp + (size_t)row * NDIM, NDIM * 4, mb);
    };

    // Prologue: fill the pipeline immediately — DRAM busy from t=0.
    if (tid == 0)
        for (int it = 0; it < DSTG && it < total; it++) issue(it);

    // Inline rate-coding encoder into sS (x,u are 32 KB, L2-shared by all blocks).
    for (int i = tid; i < NDIM; i += NTHR)
        sS[i] = (__ldg(u + i) < __ldg(x + i)) ? 1.0f : 0.0f;
    __syncthreads();

    const int Tv = Tp ? __ldg(Tp) : 128;
    const float invT = 1.0f / (float)Tv;

    int it = 0;
    for (int layer = 0; layer < 3; layer++) {
        if (layer) {
            // Device barrier; next-layer TMAs already in flight across it.
            grid_bar(base + layer);
            const float* gs = (layer == 1) ? g_s0 : g_s1;
            for (int i = tid; i < NDIM / 4; i += NTHR)
                ((float4*)sS)[i] = ((const float4*)gs)[i];
            __syncthreads();
        }
        for (int j = 0; j < c; j++, it++) {
            const int stage = it & (DSTG - 1);
            mbar_wait(mbar0 + stage * 8, (it / DSTG) & 1);

            const float4* w4 = (const float4*)(sm + stage * STG_BYTES);
            const float4* m4 = w4 + NDIM / 4;
            const float4* s4 = (const float4*)sS;

            float a0 = 0.0f, a1 = 0.0f;
#pragma unroll
            for (int k = 0; k < 4; k += 2) {
                const int i0 = tid + (k + 0) * NTHR;
                const int i1 = tid + (k + 1) * NTHR;
                const float4 w0 = w4[i0], m0 = m4[i0], v0 = s4[i0];
                const float4 w1 = w4[i1], m1 = m4[i1], v1 = s4[i1];
                a0 = fmaf(w0.x * m0.x, v0.x, a0);
                a0 = fmaf(w0.y * m0.y, v0.y, a0);
                a0 = fmaf(w0.z * m0.z, v0.z, a0);
                a0 = fmaf(w0.w * m0.w, v0.w, a0);
                a1 = fmaf(w1.x * m1.x, v1.x, a1);
                a1 = fmaf(w1.y * m1.y, v1.y, a1);
                a1 = fmaf(w1.z * m1.z, v1.z, a1);
                a1 = fmaf(w1.w * m1.w, v1.w, a1);
            }
            float acc = a0 + a1;
#pragma unroll
            for (int o = 16; o; o >>= 1) acc += __shfl_xor_sync(0xffffffffu, acc, o);
            if ((tid & 31) == 0) red[tid >> 5] = acc;
            __syncthreads();

            if (tid == 0) {
                float t = 0.0f;
#pragma unroll
                for (int i = 0; i < 8; i++) t += red[i];
                const float spk = (t > 1.0f) ? 1.0f : 0.0f;   // THRESH = 1.0
                const int row = bid + GRID * j;
                if (layer == 0)      g_s0[row] = spk;
                else if (layer == 1) g_s1[row] = spk;
                else                 out[row] = spk * invT;   // spikes only at t=0
            }
            __syncthreads();                     // stage fully consumed
            if (tid == 0 && it + DSTG < total) { // refill this stage
                fence_proxy_async_s();
                issue(it + DSTG);
            }
        }
    }
}

extern "C" void kernel_launch(void* const* d_in, const int* in_sizes, int n_in,
                              void* d_out, int out_size) {
    const float* x  = (const float*)d_in[0];
    const float* u  = (const float*)d_in[1];
    const float* W0 = (const float*)d_in[2];
    const float* W1 = (const float*)d_in[3];
    const float* W2 = (const float*)d_in[4];
    const float* M0 = (const float*)d_in[5];
    const float* M1 = (const float*)d_in[6];
    const float* M2 = (const float*)d_in[7];
    const int*   T  = (n_in > 8) ? (const int*)d_in[8] : nullptr;
    float* out = (float*)d_out;

    cudaFuncSetAttribute(snn_k, cudaFuncAttributeMaxDynamicSharedMemorySize,
                         SMEM_BYTES);
    snn_k<<<GRID, NTHR, SMEM_BYTES>>>(x, u, W0, W1, W2, M0, M1, M2, T, out);
}

// round 12
// speedup vs baseline: 1.1801x; 1.1801x over previous
#include <cuda_runtime.h>

#define NDIM 4096

// Inter-layer spike vectors (scratch via __device__ globals — no allocation).
__device__ float g_s0[NDIM];
__device__ float g_s1[NDIM];

// Layer 0: masked matvec against on-the-fly rate-coded encoding.
// enc_j = (u_j < x_j) ? 1 : 0 computed inline from L2-resident x,u —
// no separate encoder kernel, no smem staging, no extra syncs.
__global__ __launch_bounds__(256) void layer0_k(const float* __restrict__ x,
                                                const float* __restrict__ u,
                                                const float* __restrict__ W,
                                                const float* __restrict__ M) {
    const int row = blockIdx.x;
    const float4* __restrict__ w4 = (const float4*)W + (size_t)row * (NDIM / 4);
    const float4* __restrict__ m4 = (const float4*)M + (size_t)row * (NDIM / 4);
    const float4* __restrict__ x4 = (const float4*)x;
    const float4* __restrict__ u4 = (const float4*)u;

    float a0 = 0.0f, a1 = 0.0f;
#pragma unroll
    for (int k = 0; k < 4; k += 2) {
        const int i0 = threadIdx.x + (k + 0) * 256;
        const int i1 = threadIdx.x + (k + 1) * 256;
        const float4 w0 = __ldcs(w4 + i0);
        const float4 m0 = __ldcs(m4 + i0);
        const float4 w1 = __ldcs(w4 + i1);
        const float4 m1 = __ldcs(m4 + i1);
        const float4 xa = __ldg(x4 + i0), ua = __ldg(u4 + i0);
        const float4 xb = __ldg(x4 + i1), ub = __ldg(u4 + i1);
        a0 += (ua.x < xa.x) ? w0.x * m0.x : 0.0f;
        a0 += (ua.y < xa.y) ? w0.y * m0.y : 0.0f;
        a0 += (ua.z < xa.z) ? w0.z * m0.z : 0.0f;
        a0 += (ua.w < xa.w) ? w0.w * m0.w : 0.0f;
        a1 += (ub.x < xb.x) ? w1.x * m1.x : 0.0f;
        a1 += (ub.y < xb.y) ? w1.y * m1.y : 0.0f;
        a1 += (ub.z < xb.z) ? w1.z * m1.z : 0.0f;
        a1 += (ub.w < xb.w) ? w1.w * m1.w : 0.0f;
    }

    float acc = a0 + a1;
#pragma unroll
    for (int o = 16; o; o >>= 1) acc += __shfl_xor_sync(0xffffffffu, acc, o);

    __shared__ float sm[8];
    if ((threadIdx.x & 31) == 0) sm[threadIdx.x >> 5] = acc;
    __syncthreads();
    if (threadIdx.x == 0) {
        float t = 0.0f;
#pragma unroll
        for (int i = 0; i < 8; i++) t += sm[i];
        g_s0[row] = (t > 1.0f) ? 1.0f : 0.0f;   // THRESH = 1.0
    }
}

// Layers 1/2 with PDL: first batch of W/M loads is issued BEFORE
// cudaGridDependencySynchronize() — it has no dependency on the previous
// layer's spikes — so the DRAM pipe stays full across the kernel boundary.
//  IN : 0 -> g_s0, 1 -> g_s1.  FINAL: write out[row] = spk / T.
template<int IN, int FINAL>
__global__ __launch_bounds__(256) void layerN_k(const float* __restrict__ W,
                                                const float* __restrict__ M,
                                                const int* __restrict__ Tp,
                                                float* __restrict__ out) {
    const int row = blockIdx.x;
    const float4* __restrict__ w4 = (const float4*)W + (size_t)row * (NDIM / 4);
    const float4* __restrict__ m4 = (const float4*)M + (size_t)row * (NDIM / 4);

    const int i0 = threadIdx.x;
    const int i1 = threadIdx.x + 256;
    const int i2 = threadIdx.x + 512;
    const int i3 = threadIdx.x + 768;

    // Batch 0: spike-independent DRAM loads, in flight across the PDL edge.
    const float4 w0 = __ldcs(w4 + i0);
    const float4 m0 = __ldcs(m4 + i0);
    const float4 w1 = __ldcs(w4 + i1);
    const float4 m1 = __ldcs(m4 + i1);

    // Wait for the previous layer's grid (spike vector becomes valid).
    cudaGridDependencySynchronize();

    const float* s = (IN == 0) ? g_s0 : g_s1;
    const float4* __restrict__ s4 = (const float4*)s;
    const float4 v0 = __ldg(s4 + i0);
    const float4 v1 = __ldg(s4 + i1);

    // Batch 1 loads overlap batch-0 FMAs.
    const float4 w2 = __ldcs(w4 + i2);
    const float4 m2 = __ldcs(m4 + i2);
    const float4 w3 = __ldcs(w4 + i3);
    const float4 m3 = __ldcs(m4 + i3);

    float a0 = 0.0f, a1 = 0.0f;
    a0 = fmaf(w0.x * m0.x, v0.x, a0); a0 = fmaf(w0.y * m0.y, v0.y, a0);
    a0 = fmaf(w0.z * m0.z, v0.z, a0); a0 = fmaf(w0.w * m0.w, v0.w, a0);
    a1 = fmaf(w1.x * m1.x, v1.x, a1); a1 = fmaf(w1.y * m1.y, v1.y, a1);
    a1 = fmaf(w1.z * m1.z, v1.z, a1); a1 = fmaf(w1.w * m1.w, v1.w, a1);

    const float4 v2 = __ldg(s4 + i2);
    const float4 v3 = __ldg(s4 + i3);
    a0 = fmaf(w2.x * m2.x, v2.x, a0); a0 = fmaf(w2.y * m2.y, v2.y, a0);
    a0 = fmaf(w2.z * m2.z, v2.z, a0); a0 = fmaf(w2.w * m2.w, v2.w, a0);
    a1 = fmaf(w3.x * m3.x, v3.x, a1); a1 = fmaf(w3.y * m3.y, v3.y, a1);
    a1 = fmaf(w3.z * m3.z, v3.z, a1); a1 = fmaf(w3.w * m3.w, v3.w, a1);

    float acc = a0 + a1;
#pragma unroll
    for (int o = 16; o; o >>= 1) acc += __shfl_xor_sync(0xffffffffu, acc, o);

    __shared__ float sm[8];
    if ((threadIdx.x & 31) == 0) sm[threadIdx.x >> 5] = acc;
    __syncthreads();
    if (threadIdx.x == 0) {
        float t = 0.0f;
#pragma unroll
        for (int i = 0; i < 8; i++) t += sm[i];
        const float spk = (t > 1.0f) ? 1.0f : 0.0f;   // THRESH = 1.0
        if (!FINAL) {
            g_s1[row] = spk;
        } else {
            const int T = Tp ? *Tp : 128;
            out[row] = spk / (float)T;                // spikes only at t=0
        }
    }
}

extern "C" void kernel_launch(void* const* d_in, const int* in_sizes, int n_in,
                              void* d_out, int out_size) {
    const float* x  = (const float*)d_in[0];
    const float* u  = (const float*)d_in[1];
    const float* W0 = (const float*)d_in[2];
    const float* W1 = (const float*)d_in[3];
    const float* W2 = (const float*)d_in[4];
    const float* M0 = (const float*)d_in[5];
    const float* M1 = (const float*)d_in[6];
    const float* M2 = (const float*)d_in[7];
    const int*   T  = (n_in > 8) ? (const int*)d_in[8] : nullptr;
    float* out = (float*)d_out;

    layer0_k<<<NDIM, 256>>>(x, u, W0, M0);

    cudaLaunchAttribute attr[1];
    attr[0].id = cudaLaunchAttributeProgrammaticStreamSerialization;
    attr[0].val.programmaticStreamSerializationAllowed = 1;

    cudaLaunchConfig_t cfg = {};
    cfg.gridDim  = dim3(NDIM, 1, 1);
    cfg.blockDim = dim3(256, 1, 1);
    cfg.dynamicSmemBytes = 0;
    cfg.stream = 0;
    cfg.attrs = attr;
    cfg.numAttrs = 1;

    cudaLaunchKernelEx(&cfg, layerN_k<0, 0>, W1, M1, (const int*)nullptr,
                       (float*)nullptr);
    cudaLaunchKernelEx(&cfg, layerN_k<1, 1>, W2, M2, T, out);
}

// round 13
// speedup vs baseline: 1.1922x; 1.0102x over previous
#include <cuda_runtime.h>

#define NDIM 4096

// Inter-layer spike vectors (scratch via __device__ globals — no allocation).
__device__ float g_s0[NDIM];
__device__ float g_s1[NDIM];

// Layer 0: masked matvec against on-the-fly rate-coded encoding.
// enc_j = (u_j < x_j) ? 1 : 0 computed inline from L2-resident x,u.
__global__ __launch_bounds__(256) void layer0_k(const float* __restrict__ x,
                                                const float* __restrict__ u,
                                                const float* __restrict__ W,
                                                const float* __restrict__ M) {
    const int row = blockIdx.x;
    const float4* __restrict__ w4 = (const float4*)W + (size_t)row * (NDIM / 4);
    const float4* __restrict__ m4 = (const float4*)M + (size_t)row * (NDIM / 4);
    const float4* __restrict__ x4 = (const float4*)x;
    const float4* __restrict__ u4 = (const float4*)u;

    float a0 = 0.0f, a1 = 0.0f;
#pragma unroll
    for (int k = 0; k < 4; k += 2) {
        const int i0 = threadIdx.x + (k + 0) * 256;
        const int i1 = threadIdx.x + (k + 1) * 256;
        const float4 w0 = __ldcs(w4 + i0);
        const float4 m0 = __ldcs(m4 + i0);
        const float4 w1 = __ldcs(w4 + i1);
        const float4 m1 = __ldcs(m4 + i1);
        const float4 xa = __ldg(x4 + i0), ua = __ldg(u4 + i0);
        const float4 xb = __ldg(x4 + i1), ub = __ldg(u4 + i1);
        a0 += (ua.x < xa.x) ? w0.x * m0.x : 0.0f;
        a0 += (ua.y < xa.y) ? w0.y * m0.y : 0.0f;
        a0 += (ua.z < xa.z) ? w0.z * m0.z : 0.0f;
        a0 += (ua.w < xa.w) ? w0.w * m0.w : 0.0f;
        a1 += (ub.x < xb.x) ? w1.x * m1.x : 0.0f;
        a1 += (ub.y < xb.y) ? w1.y * m1.y : 0.0f;
        a1 += (ub.z < xb.z) ? w1.z * m1.z : 0.0f;
        a1 += (ub.w < xb.w) ? w1.w * m1.w : 0.0f;
    }

    float acc = a0 + a1;
#pragma unroll
    for (int o = 16; o; o >>= 1) acc += __shfl_xor_sync(0xffffffffu, acc, o);

    __shared__ float sm[8];
    if ((threadIdx.x & 31) == 0) sm[threadIdx.x >> 5] = acc;
    __syncthreads();
    if (threadIdx.x == 0) {
        float t = 0.0f;
#pragma unroll
        for (int i = 0; i < 8; i++) t += sm[i];
        g_s0[row] = (t > 1.0f) ? 1.0f : 0.0f;   // THRESH = 1.0
    }
}

// Layers 1/2 with PDL: the ENTIRE 32 KB W/M row pair is issued BEFORE
// cudaGridDependencySynchronize() (spike-independent), so early-launched
// blocks saturate DRAM across the whole kernel boundary window.
//  IN : 0 -> g_s0, 1 -> g_s1.  FINAL: write out[row] = spk / T.
template<int IN, int FINAL>
__global__ __launch_bounds__(256) void layerN_k(const float* __restrict__ W,
                                                const float* __restrict__ M,
                                                const int* __restrict__ Tp,
                                                float* __restrict__ out) {
    const int row = blockIdx.x;
    const float4* __restrict__ w4 = (const float4*)W + (size_t)row * (NDIM / 4);
    const float4* __restrict__ m4 = (const float4*)M + (size_t)row * (NDIM / 4);

    const int i0 = threadIdx.x;
    const int i1 = threadIdx.x + 256;
    const int i2 = threadIdx.x + 512;
    const int i3 = threadIdx.x + 768;

    // All spike-independent DRAM loads, in flight across the PDL edge.
    const float4 w0 = __ldcs(w4 + i0);
    const float4 m0 = __ldcs(m4 + i0);
    const float4 w1 = __ldcs(w4 + i1);
    const float4 m1 = __ldcs(m4 + i1);
    const float4 w2 = __ldcs(w4 + i2);
    const float4 m2 = __ldcs(m4 + i2);
    const float4 w3 = __ldcs(w4 + i3);
    const float4 m3 = __ldcs(m4 + i3);

    // Wait for the previous layer's grid (spike vector becomes valid).
    cudaGridDependencySynchronize();

    const float* s = (IN == 0) ? g_s0 : g_s1;
    const float4* __restrict__ s4 = (const float4*)s;
    const float4 v0 = __ldg(s4 + i0);
    const float4 v1 = __ldg(s4 + i1);
    const float4 v2 = __ldg(s4 + i2);
    const float4 v3 = __ldg(s4 + i3);

    float a0 = 0.0f, a1 = 0.0f;
    a0 = fmaf(w0.x * m0.x, v0.x, a0); a0 = fmaf(w0.y * m0.y, v0.y, a0);
    a0 = fmaf(w0.z * m0.z, v0.z, a0); a0 = fmaf(w0.w * m0.w, v0.w, a0);
    a1 = fmaf(w1.x * m1.x, v1.x, a1); a1 = fmaf(w1.y * m1.y, v1.y, a1);
    a1 = fmaf(w1.z * m1.z, v1.z, a1); a1 = fmaf(w1.w * m1.w, v1.w, a1);
    a0 = fmaf(w2.x * m2.x, v2.x, a0); a0 = fmaf(w2.y * m2.y, v2.y, a0);
    a0 = fmaf(w2.z * m2.z, v2.z, a0); a0 = fmaf(w2.w * m2.w, v2.w, a0);
    a1 = fmaf(w3.x * m3.x, v3.x, a1); a1 = fmaf(w3.y * m3.y, v3.y, a1);
    a1 = fmaf(w3.z * m3.z, v3.z, a1); a1 = fmaf(w3.w * m3.w, v3.w, a1);

    float acc = a0 + a1;
#pragma unroll
    for (int o = 16; o; o >>= 1) acc += __shfl_xor_sync(0xffffffffu, acc, o);

    __shared__ float sm[8];
    if ((threadIdx.x & 31) == 0) sm[threadIdx.x >> 5] = acc;
    __syncthreads();
    if (threadIdx.x == 0) {
        float t = 0.0f;
#pragma unroll
        for (int i = 0; i < 8; i++) t += sm[i];
        const float spk = (t > 1.0f) ? 1.0f : 0.0f;   // THRESH = 1.0
        if (!FINAL) {
            g_s1[row] = spk;
        } else {
            const int T = Tp ? *Tp : 128;
            out[row] = spk / (float)T;                // spikes only at t=0
        }
    }
}

extern "C" void kernel_launch(void* const* d_in, const int* in_sizes, int n_in,
                              void* d_out, int out_size) {
    const float* x  = (const float*)d_in[0];
    const float* u  = (const float*)d_in[1];
    const float* W0 = (const float*)d_in[2];
    const float* W1 = (const float*)d_in[3];
    const float* W2 = (const float*)d_in[4];
    const float* M0 = (const float*)d_in[5];
    const float* M1 = (const float*)d_in[6];
    const float* M2 = (const float*)d_in[7];
    const int*   T  = (n_in > 8) ? (const int*)d_in[8] : nullptr;
    float* out = (float*)d_out;

    layer0_k<<<NDIM, 256>>>(x, u, W0, M0);

    cudaLaunchAttribute attr[1];
    attr[0].id = cudaLaunchAttributeProgrammaticStreamSerialization;
    attr[0].val.programmaticStreamSerializationAllowed = 1;

    cudaLaunchConfig_t cfg = {};
    cfg.gridDim  = dim3(NDIM, 1, 1);
    cfg.blockDim = dim3(256, 1, 1);
    cfg.dynamicSmemBytes = 0;
    cfg.stream = 0;
    cfg.attrs = attr;
    cfg.numAttrs = 1;

    cudaLaunchKernelEx(&cfg, layerN_k<0, 0>, W1, M1, (const int*)nullptr,
                       (float*)nullptr);
    cudaLaunchKernelEx(&cfg, layerN_k<1, 1>, W2, M2, T, out);
}